// round 2
// baseline (speedup 1.0000x reference)
#include <cuda_runtime.h>
#include <cstdint>

// out[o*256+k][h][m] = sum_{i,j} w[i][k][j] * pad(xr)[m+j]   (rolls baked into indexing)
// Grid (ich=4, okt=4, h=14) = 224 blocks x 128 threads; thread = one k, 7 f32x2 accumulators.
// Partials -> __device__ scratch, float4 reduce kernel.

#define ICH   4
#define ILEN  64
#define KB    128

__device__ float g_partial[ICH * 512 * 196];

__device__ __forceinline__ uint64_t pk2(float lo, float hi) {
    uint64_t r;
    asm("mov.b64 %0, {%1, %2};" : "=l"(r) : "r"(__float_as_uint(lo)), "r"(__float_as_uint(hi)));
    return r;
}

__device__ __forceinline__ uint64_t ffma2(uint64_t a, uint64_t b, uint64_t c) {
    uint64_t d;
    asm("fma.rn.f32x2 %0, %1, %2, %3;" : "=l"(d) : "l"(a), "l"(b), "l"(c));
    return d;
}

__global__ __launch_bounds__(128) void conv_kernel(const float* __restrict__ x,
                                                   const float* __restrict__ w) {
    const int ich = blockIdx.x;          // i chunk
    const int okt = blockIdx.y;          // o = okt>>1, kt = okt&1
    const int h   = blockIdx.z;          // output row (post H-roll)
    const int o   = okt >> 1;
    const int kt  = okt & 1;
    const int tx  = threadIdx.x;
    const int k   = kt * KB + tx;
    const int n   = (h + 13) % 14;       // source H row (undo roll along H)

    // sxe[il][mm] = padded/rolled row value at tap-position mm   (mm in 0..15)
    // sxo[il][mm] = same row shifted by +1 (value at mm+1)       -> odd pairs load as u64
    __shared__ float sxe[ILEN][16];
    __shared__ float sxo[ILEN][16];

    const float* xrow = x + ((size_t)(o * 256 + ich * ILEN) * 14 + n) * 14;
    for (int idx = tx; idx < ILEN * 16; idx += 128) {
        const int il = idx >> 4;
        const int mm = idx & 15;
        // padded(mm): mm in [1,14] -> x[il-row][(mm+12)%14], else 0
        float ve = 0.f, vo = 0.f;
        if (mm >= 1 && mm <= 14)
            ve = xrow[(size_t)il * 196 + (mm + 12) % 14];
        if (mm <= 13)   // padded(mm+1), mm+1 in [1,14]
            vo = xrow[(size_t)il * 196 + (mm + 13) % 14];
        sxe[il][mm] = ve;
        sxo[il][mm] = vo;
    }
    __syncthreads();

    uint64_t A[7];
#pragma unroll
    for (int p = 0; p < 7; p++) A[p] = 0ull;

    const float* wp = w + ((size_t)(ich * ILEN) * 256 + k) * 3;

#pragma unroll 4
    for (int il = 0; il < ILEN; ++il) {
        const float w0 = wp[0];
        const float w1 = wp[1];
        const float w2 = wp[2];
        wp += 256 * 3;
        const uint64_t W0 = pk2(w0, w0);
        const uint64_t W1 = pk2(w1, w1);
        const uint64_t W2 = pk2(w2, w2);

        // E[p] = {xr[2p], xr[2p+1]}  p=0..7 ; O[p] = {xr[2p+1], xr[2p+2]} p=0..6
        const ulonglong2 e01 = *(const ulonglong2*)&sxe[il][0];
        const ulonglong2 e23 = *(const ulonglong2*)&sxe[il][4];
        const ulonglong2 e45 = *(const ulonglong2*)&sxe[il][8];
        const ulonglong2 e67 = *(const ulonglong2*)&sxe[il][12];
        const ulonglong2 o01 = *(const ulonglong2*)&sxo[il][0];
        const ulonglong2 o23 = *(const ulonglong2*)&sxo[il][4];
        const ulonglong2 o45 = *(const ulonglong2*)&sxo[il][8];
        const ulonglong2 o6_ = *(const ulonglong2*)&sxo[il][12];

        uint64_t E[8] = {e01.x, e01.y, e23.x, e23.y, e45.x, e45.y, e67.x, e67.y};
        uint64_t O[7] = {o01.x, o01.y, o23.x, o23.y, o45.x, o45.y, o6_.x};

#pragma unroll
        for (int p = 0; p < 7; p++) {
            A[p] = ffma2(W0, E[p],     A[p]);
            A[p] = ffma2(W1, O[p],     A[p]);
            A[p] = ffma2(W2, E[p + 1], A[p]);
        }
    }

    // partial layout: [ich][c=o*256+k][196]; per-thread 14 contiguous floats (8B aligned)
    float* pp = g_partial + ((size_t)(ich * 512 + o * 256 + k) * 196 + h * 14);
#pragma unroll
    for (int p = 0; p < 7; p++)
        *(uint64_t*)&pp[2 * p] = A[p];
}

__global__ __launch_bounds__(256) void reduce_kernel(float* __restrict__ out) {
    const int t = blockIdx.x * 256 + threadIdx.x;   // float4 index, 25088 total
    if (t < 512 * 196 / 4) {
        const float4* p0 = (const float4*)g_partial;
        const float4 a = p0[t];
        const float4 b = p0[1 * 512 * 196 / 4 + t];
        const float4 c = p0[2 * 512 * 196 / 4 + t];
        const float4 d = p0[3 * 512 * 196 / 4 + t];
        float4 s;
        s.x = (a.x + b.x) + (c.x + d.x);
        s.y = (a.y + b.y) + (c.y + d.y);
        s.z = (a.z + b.z) + (c.z + d.z);
        s.w = (a.w + b.w) + (c.w + d.w);
        ((float4*)out)[t] = s;
    }
}

extern "C" void kernel_launch(void* const* d_in, const int* in_sizes, int n_in,
                              void* d_out, int out_size) {
    const float* x = (const float*)d_in[0];   // (1,512,14,14)
    const float* w = (const float*)d_in[1];   // (256,256,3)
    float* out = (float*)d_out;

    dim3 grid(ICH, 4, 14);
    conv_kernel<<<grid, 128>>>(x, w);
    reduce_kernel<<<(512 * 196 / 4 + 255) / 256, 256>>>(out);
}